// round 7
// baseline (speedup 1.0000x reference)
#include <cuda_runtime.h>
#include <cuda_bf16.h>
#include <cstdint>

#define B_ 4
#define T_ 2048
#define H_ 16
#define D_ 128
#define HD 2048        // H_*D_
#define S_ 16          // steps per chunk
#define NC (T_/S_)     // 128 chunks

// smem layout (float offsets). q/f double-buffered (cp.async), kg/vg single.
// qf buffer b at b*5120: q tile at +0, f tile at +2560
#define KG_OFF 10240   // kg rows: 16 t * 160
#define VG_OFF 12800   // vg cols: 16 t * 32
#define SM_FLOATS 13312
#define SM_BYTES  53248

typedef unsigned long long u64;

__device__ __forceinline__ u64 pk2(float x, float y) {
    u64 r; asm("mov.b64 %0,{%1,%2};" : "=l"(r) : "f"(x), "f"(y)); return r;
}
__device__ __forceinline__ float2 up2(u64 a) {
    float2 r; asm("mov.b64 {%0,%1},%2;" : "=f"(r.x), "=f"(r.y) : "l"(a)); return r;
}
__device__ __forceinline__ u64 mul2(u64 a, u64 b) {
    u64 d; asm("mul.rn.f32x2 %0,%1,%2;" : "=l"(d) : "l"(a), "l"(b)); return d;
}
__device__ __forceinline__ u64 add2(u64 a, u64 b) {
    u64 d; asm("add.rn.f32x2 %0,%1,%2;" : "=l"(d) : "l"(a), "l"(b)); return d;
}
__device__ __forceinline__ u64 fma2(u64 a, u64 b, u64 c) {
    u64 d; asm("fma.rn.f32x2 %0,%1,%2,%3;" : "=l"(d) : "l"(a), "l"(b), "l"(c)); return d;
}
__device__ __forceinline__ u64 max2c(u64 a, float c) {
    float2 t = up2(a);
    t.x = fmaxf(t.x, c); t.y = fmaxf(t.y, c);
    return pk2(t.x, t.y);
}
__device__ __forceinline__ void cp16(uint32_t dst, const float* src) {
    asm volatile("cp.async.cg.shared.global [%0], [%1], 16;" :: "r"(dst), "l"(src) : "memory");
}
__device__ __forceinline__ uint32_t s2u(const void* p) {
    uint32_t a;
    asm("{ .reg .u64 t; cvta.to.shared.u64 t, %1; cvt.u32.u64 %0, t; }" : "=r"(a) : "l"(p));
    return a;
}

// Row tile per t: 8 blocks of (16 floats + 4 pad) = 160 floats.
// Granule a (rows 4a..4a+3) at t*160 + (a>>2)*20 + (a&3)*4 -> conflict-free LDS.128.
__global__ __launch_bounds__(256, 2) void delta_kernel(
    const float* __restrict__ q, const float* __restrict__ k,
    const float* __restrict__ v, const float* __restrict__ f,
    const float* __restrict__ g, float* __restrict__ out)
{
    extern __shared__ float smp[];
    const uint32_t smem0 = s2u(smp);

    const int tid  = threadIdx.x;
    const int w    = tid >> 5, lane = tid & 31;
    const int r    = lane >> 2;          // 8 row-groups of 16 rows
    const int c    = lane & 3;           // 4 columns per warp
    const int colbase = blockIdx.x * 32; // 32 columns per CTA
    const long base0  = (long)blockIdx.z * T_ * HD + (long)blockIdx.y * D_;

    // staging roles: t_s in [0,16), u in [0,16); thread owns rows u*8..u*8+7 of t_s
    const int  t_s = tid >> 4, u = tid & 15;
    const long grow = base0 + (long)t_s * HD + u * 8;
    const int  ccol = u * 2;             // 2 cols per thread
    const long gcol = base0 + (long)t_s * HD + colbase + ccol;
    const int  soff = t_s * 160 + (u >> 1) * 20 + (u & 1) * 8;   // 2 adjacent granules
    const uint32_t d_soff = (uint32_t)soff * 4;

    // compute constants
    const int rl  = r * 20;
    const int dj  = colbase + w * 4 + c;                 // global column [0,128)
    const int fcidx = (dj >> 4) * 20 + (dj & 15);
    const int vcidx = w * 4 + c;                         // [0,32)
    float* outp = out + base0 + dj;

    // prime: cp q,f chunk0 -> qf buffer 0; LDG k,g,v,gc regs for chunk 0
    {
        cp16(smem0 + d_soff,           q + grow);
        cp16(smem0 + d_soff + 16,      q + grow + 4);
        cp16(smem0 + 2560 * 4 + d_soff,      f + grow);
        cp16(smem0 + 2560 * 4 + d_soff + 16, f + grow + 4);
        asm volatile("cp.async.commit_group;" ::: "memory");
    }
    float4 k0 = *(const float4*)(k + grow), k1 = *(const float4*)(k + grow + 4);
    float4 g0 = *(const float4*)(g + grow), g1 = *(const float4*)(g + grow + 4);
    float2 cv = *(const float2*)(v + gcol), cg = *(const float2*)(g + gcol);

    u64 M[8];
#pragma unroll
    for (int p = 0; p < 8; p++) M[p] = 0ull;

    for (int ch = 0; ch < NC; ch++) {
        const float* bufqf = smp + (ch & 1) * 5120;
        // ---- stage kg, vg from regs (prev compute done per loop-end sync) ----
        {
            float4 kg0, kg1;
            kg0.x = k0.x * g0.x; kg0.y = k0.y * g0.y;
            kg0.z = k0.z * g0.z; kg0.w = k0.w * g0.w;
            kg1.x = k1.x * g1.x; kg1.y = k1.y * g1.y;
            kg1.z = k1.z * g1.z; kg1.w = k1.w * g1.w;
            *(float4*)(smp + KG_OFF + soff)     = kg0;
            *(float4*)(smp + KG_OFF + soff + 4) = kg1;
            *(float2*)(smp + VG_OFF + t_s * 32 + ccol) = make_float2(cv.x * cg.x, cv.y * cg.y);
        }
        asm volatile("cp.async.wait_group 0;" ::: "memory");
        __syncthreads();
        // ---- issue next chunk's loads (overlap compute) ----
        if (ch + 1 < NC) {
            const long off = (long)(ch + 1) * S_ * HD;
            const uint32_t bq = smem0 + (uint32_t)((ch + 1) & 1) * 5120 * 4;
            cp16(bq + d_soff,                q + grow + off);
            cp16(bq + d_soff + 16,           q + grow + off + 4);
            cp16(bq + 2560 * 4 + d_soff,      f + grow + off);
            cp16(bq + 2560 * 4 + d_soff + 16, f + grow + off + 4);
            asm volatile("cp.async.commit_group;" ::: "memory");
            k0 = *(const float4*)(k + grow + off); k1 = *(const float4*)(k + grow + off + 4);
            g0 = *(const float4*)(g + grow + off); g1 = *(const float4*)(g + grow + off + 4);
            cv = *(const float2*)(v + gcol + off); cg = *(const float2*)(g + gcol + off);
        }
        // ---- compute 16 steps ----
#pragma unroll
        for (int s = 0; s < S_; s++) {
            const float* qb = bufqf + s * 160 + rl;
            const float* fb = bufqf + 2560 + s * 160 + rl;
            const float* kb = smp + KG_OFF + s * 160 + rl;
            const float fc  = bufqf[2560 + s * 160 + fcidx];
            const float vgc = smp[VG_OFF + s * 32 + vcidx];
            const u64 fj = pk2(fc, fc);
            const u64 vj = pk2(vgc, vgc);
            u64 oa = 0ull, ob = 0ull;
#pragma unroll
            for (int l = 0; l < 4; l++) {
                float4 f4 = *(const float4*)(fb + l * 4);
                float4 k4 = *(const float4*)(kb + l * 4);
                float4 q4 = *(const float4*)(qb + l * 4);
                u64 fo, wv;
                fo = max2c(mul2(pk2(f4.x, f4.y), fj), 0.8f);
                wv = mul2(pk2(k4.x, k4.y), vj);
                M[l * 2] = fma2(M[l * 2], fo, wv);
                oa = fma2(pk2(q4.x, q4.y), M[l * 2], oa);
                fo = max2c(mul2(pk2(f4.z, f4.w), fj), 0.8f);
                wv = mul2(pk2(k4.z, k4.w), vj);
                M[l * 2 + 1] = fma2(M[l * 2 + 1], fo, wv);
                ob = fma2(pk2(q4.z, q4.w), M[l * 2 + 1], ob);
            }
            const float2 oo = up2(add2(oa, ob));
            float osum = oo.x + oo.y;
            osum += __shfl_xor_sync(0xffffffffu, osum, 4);
            osum += __shfl_xor_sync(0xffffffffu, osum, 8);
            osum += __shfl_xor_sync(0xffffffffu, osum, 16);
            if (lane < 4) outp[s * HD] = osum;
        }
        outp += S_ * HD;
        __syncthreads();   // all reads of kg/vg done before next staging overwrites
    }
}

extern "C" void kernel_launch(void* const* d_in, const int* in_sizes, int n_in,
                              void* d_out, int out_size) {
    const float* q = (const float*)d_in[0];
    const float* k = (const float*)d_in[1];
    const float* v = (const float*)d_in[2];
    const float* f = (const float*)d_in[3];
    const float* g = (const float*)d_in[4];
    cudaFuncSetAttribute(delta_kernel,
                         cudaFuncAttributeMaxDynamicSharedMemorySize, SM_BYTES);
    dim3 grid(4, H_, B_);
    delta_kernel<<<grid, 256, SM_BYTES>>>(q, k, v, f, g, (float*)d_out);
}